// round 8
// baseline (speedup 1.0000x reference)
#include <cuda_runtime.h>
#include <cstdint>

// ---------------------------------------------------------------------------
// Single fused kernel:
//   prologue: issue first TMA prefetch, then compose the 8 conv layers into
//             one affine map A (9x10, padded to 9x12) in smem, per block.
//   loop:     persistent double-buffered TMA pipeline over 512-row tiles:
//             prefetch next (wait_group.read gate) -> mbarrier wait ->
//             in-place vector compute -> async bulk store (no wait).
// ---------------------------------------------------------------------------
#define TPB 128
#define RPT 4
#define ROWS_PER_TILE (TPB * RPT)            // 512
#define WORDS_PER_TILE (ROWS_PER_TILE * 9)   // 4608
#define BYTES_PER_TILE (WORDS_PER_TILE * 4)  // 18432

__device__ __forceinline__ uint32_t smem_u32(const void* p) {
    uint32_t a;
    asm("{ .reg .u64 tmp; cvta.to.shared.u64 tmp, %1; cvt.u32.u64 %0, tmp; }"
        : "=r"(a) : "l"(p));
    return a;
}

__device__ __forceinline__ void mbar_wait(uint32_t mb, uint32_t parity) {
    uint32_t done;
    asm volatile(
        "{\n\t.reg .pred p;\n\t"
        "mbarrier.try_wait.parity.acquire.cta.shared::cta.b64 p, [%1], %2;\n\t"
        "selp.b32 %0, 1, 0, p;\n\t}"
        : "=r"(done) : "r"(mb), "r"(parity) : "memory");
    if (!done) {
        asm volatile(
            "{\n\t.reg .pred P1;\n\t"
            "WAIT_LOOP_%=:\n\t"
            "mbarrier.try_wait.parity.acquire.cta.shared::cta.b64 P1, [%0], %1, 0x989680;\n\t"
            "@P1 bra.uni WAIT_DONE_%=;\n\t"
            "bra.uni WAIT_LOOP_%=;\n\t"
            "WAIT_DONE_%=:\n\t}"
            :: "r"(mb), "r"(parity) : "memory");
    }
}

__global__ __launch_bounds__(TPB, 6)
void affine_kernel(const float* __restrict__ x,
                   const float* __restrict__ w,   // [8*9]
                   const float* __restrict__ bia, // [8]
                   float* __restrict__ out,
                   int nrows) {
    __shared__ __align__(128) float sx[2][WORDS_PER_TILE];
    __shared__ __align__(16) float sA[9 * 12];
    __shared__ float sM[2][9][10];
    __shared__ __align__(8) unsigned long long mbar[2];

    int t = threadIdx.x;
    int ntiles = (nrows + ROWS_PER_TILE - 1) / ROWS_PER_TILE;

    if (t == 0) {
        asm volatile("mbarrier.init.shared.b64 [%0], %1;"
                     :: "r"(smem_u32(&mbar[0])), "r"(1) : "memory");
        asm volatile("mbarrier.init.shared.b64 [%0], %1;"
                     :: "r"(smem_u32(&mbar[1])), "r"(1) : "memory");
    }
    __syncthreads();

    uint32_t s_mb0 = smem_u32(&mbar[0]);
    uint32_t s_mb1 = smem_u32(&mbar[1]);
    uint32_t s_b0  = smem_u32(sx[0]);
    uint32_t s_b1  = smem_u32(sx[1]);

    // ---- prologue: prefetch my first tile (if full) into buffer 0 ----
    {
        long long tile0 = blockIdx.x;
        if (tile0 < ntiles && t == 0) {
            long long rows0 = (long long)nrows - tile0 * ROWS_PER_TILE;
            if (rows0 >= ROWS_PER_TILE) {
                const float* xg = x + tile0 * (long long)ROWS_PER_TILE * 9;
                asm volatile("mbarrier.arrive.expect_tx.shared.b64 _, [%0], %1;"
                             :: "r"(s_mb0), "r"((uint32_t)BYTES_PER_TILE) : "memory");
                asm volatile(
                    "cp.async.bulk.shared::cta.global.mbarrier::complete_tx::bytes "
                    "[%0], [%1], %2, [%3];"
                    :: "r"(s_b0), "l"(xg), "r"((uint32_t)BYTES_PER_TILE), "r"(s_mb0)
                    : "memory");
            }
        }
    }

    // ---- compose the affine map in smem (overlaps first TMA) ----
    {
        int o = t / 10;
        int c = t % 10;
        if (t < 90) sM[0][o][c] = (c < 9 && o == c) ? 1.0f : 0.0f;
        __syncthreads();

        int cur = 0;
        for (int d = 0; d < 8; d++) {
            float acc = 0.0f;
            if (t < 90) {
                int i = o / 3, j = o % 3;
#pragma unroll
                for (int di = -1; di <= 1; di++) {
#pragma unroll
                    for (int dj = -1; dj <= 1; dj++) {
                        int ii = i + di, jj = j + dj;
                        if (ii >= 0 && ii < 3 && jj >= 0 && jj < 3) {
                            acc += w[d * 9 + (di + 1) * 3 + (dj + 1)] *
                                   sM[cur][ii * 3 + jj][c];
                        }
                    }
                }
                if (c == 9) acc += bia[d];
                sM[1 ^ cur][o][c] = acc;
            }
            __syncthreads();
            cur ^= 1;
        }

        if (t < 108) sA[t] = 0.0f;   // zero pads
        __syncthreads();
        if (t < 90) sA[o * 12 + c] = sM[cur][o][c];
        __syncthreads();
    }

    uint32_t ph[2] = {0u, 0u};
    int li = 0;
    for (long long tile = blockIdx.x; tile < ntiles; tile += gridDim.x, li++) {
        int b = li & 1;
        uint32_t s_mb_cur = b ? s_mb1 : s_mb0;
        uint32_t s_mb_nxt = b ? s_mb0 : s_mb1;
        uint32_t s_b_nxt  = b ? s_b0 : s_b1;
        float* buf = sx[b];

        long long r0 = tile * ROWS_PER_TILE;
        int rows_here = (int)((((long long)nrows - r0) < ROWS_PER_TILE)
                                  ? (nrows - r0) : ROWS_PER_TILE);
        bool full = (rows_here == ROWS_PER_TILE);
        int cnt = rows_here * 9;
        const float* xg = x + r0 * 9;
        float*       og = out + r0 * 9;

        // ---- prefetch next tile into the other buffer ----
        long long ntile = tile + gridDim.x;
        if (ntile < ntiles && t == 0) {
            long long nrows_next = (long long)nrows - ntile * ROWS_PER_TILE;
            if (nrows_next >= ROWS_PER_TILE) {
                // only need the prior store's SMEM READS done to reuse buffer
                asm volatile("cp.async.bulk.wait_group.read 0;" ::: "memory");
                const float* xgn = x + ntile * (long long)ROWS_PER_TILE * 9;
                asm volatile("mbarrier.arrive.expect_tx.shared.b64 _, [%0], %1;"
                             :: "r"(s_mb_nxt), "r"((uint32_t)BYTES_PER_TILE) : "memory");
                asm volatile(
                    "cp.async.bulk.shared::cta.global.mbarrier::complete_tx::bytes "
                    "[%0], [%1], %2, [%3];"
                    :: "r"(s_b_nxt), "l"(xgn), "r"((uint32_t)BYTES_PER_TILE), "r"(s_mb_nxt)
                    : "memory");
            }
        }

        if (full) {
            // ---- consume TMA-loaded tile ----
            mbar_wait(s_mb_cur, ph[b]);
            ph[b] ^= 1;

            float* chunk = &buf[t * 36];
            float v[20];
            float y[18];

#pragma unroll
            for (int g = 0; g < 2; g++) {
#pragma unroll
                for (int k = 0; k < 5; k++)
                    *(float4*)&v[4 * k] = *(const float4*)&chunk[16 * g + 4 * k];

                const float* xa = v + (g ? 2 : 0);
                const float* xb = xa + 9;

#pragma unroll
                for (int o = 0; o < 9; o++) {
                    float4 a0 = *(const float4*)&sA[o * 12 + 0];
                    float4 a1 = *(const float4*)&sA[o * 12 + 4];
                    float4 a2 = *(const float4*)&sA[o * 12 + 8]; // x=w8, y=bias

                    float acc = fmaf(a0.x, xa[0], a2.y);
                    acc = fmaf(a0.y, xa[1], acc);
                    acc = fmaf(a0.z, xa[2], acc);
                    acc = fmaf(a0.w, xa[3], acc);
                    acc = fmaf(a1.x, xa[4], acc);
                    acc = fmaf(a1.y, xa[5], acc);
                    acc = fmaf(a1.z, xa[6], acc);
                    acc = fmaf(a1.w, xa[7], acc);
                    y[o] = fmaf(a2.x, xa[8], acc);

                    float acd = fmaf(a0.x, xb[0], a2.y);
                    acd = fmaf(a0.y, xb[1], acd);
                    acd = fmaf(a0.z, xb[2], acd);
                    acd = fmaf(a0.w, xb[3], acd);
                    acd = fmaf(a1.x, xb[4], acd);
                    acd = fmaf(a1.y, xb[5], acd);
                    acd = fmaf(a1.z, xb[6], acd);
                    acd = fmaf(a1.w, xb[7], acd);
                    y[9 + o] = fmaf(a2.x, xb[8], acd);
                }

                if (g == 0) {
                    *(float4*)&chunk[0]  = *(const float4*)&y[0];
                    *(float4*)&chunk[4]  = *(const float4*)&y[4];
                    *(float4*)&chunk[8]  = *(const float4*)&y[8];
                    *(float4*)&chunk[12] = *(const float4*)&y[12];
                    *(float2*)&chunk[16] = *(const float2*)&y[16];
                } else {
                    *(float2*)&chunk[18] = *(const float2*)&y[0];
                    *(float4*)&chunk[20] = *(const float4*)&y[2];
                    *(float4*)&chunk[24] = *(const float4*)&y[6];
                    *(float4*)&chunk[28] = *(const float4*)&y[10];
                    *(float4*)&chunk[32] = *(const float4*)&y[14];
                }
            }

            __syncthreads();  // all y written before async store reads smem
            if (t == 0) {
                asm volatile("fence.proxy.async.shared::cta;" ::: "memory");
                asm volatile(
                    "cp.async.bulk.global.shared::cta.bulk_group [%0], [%1], %2;"
                    :: "l"(og), "r"(smem_u32(buf)), "r"((uint32_t)BYTES_PER_TILE)
                    : "memory");
                asm volatile("cp.async.bulk.commit_group;" ::: "memory");
            }
            // no wait: store drains while we move on
        } else {
            // ---- partial tile (global last tile only): synchronous path ----
            if (t == 0) {
                asm volatile("cp.async.bulk.wait_group.read 0;" ::: "memory");
            }
            __syncthreads();
#pragma unroll
            for (int k = 0; k < (WORDS_PER_TILE / (TPB * 4)); k++) {
                int fi = (k * TPB + t) * 4;
                if (fi + 4 <= cnt) {
                    *(float4*)&buf[fi] = *(const float4*)&xg[fi];
                } else if (fi < cnt) {
                    for (int u = fi; u < cnt; u++) buf[u] = xg[u];
                }
            }
            __syncthreads();
            int lr0 = t * RPT;
            for (int lr = lr0; lr < lr0 + RPT && lr < rows_here; lr++) {
                float xp[9];
#pragma unroll
                for (int c = 0; c < 9; c++) xp[c] = buf[lr * 9 + c];
#pragma unroll
                for (int o = 0; o < 9; o++) {
                    float acc = sA[o * 12 + 9];
#pragma unroll
                    for (int c = 0; c < 9; c++)
                        acc = fmaf(sA[o * 12 + c], xp[c], acc);
                    buf[lr * 9 + o] = acc;
                }
            }
            __syncthreads();
#pragma unroll
            for (int k = 0; k < (WORDS_PER_TILE / (TPB * 4)); k++) {
                int fi = (k * TPB + t) * 4;
                if (fi + 4 <= cnt) {
                    *(float4*)&og[fi] = *(const float4*)&buf[fi];
                } else if (fi < cnt) {
                    for (int u = fi; u < cnt; u++) og[u] = buf[u];
                }
            }
        }
    }

    // drain the last async store before exit
    if (t == 0) {
        asm volatile("cp.async.bulk.wait_group 0;" ::: "memory");
    }
}

extern "C" void kernel_launch(void* const* d_in, const int* in_sizes, int n_in,
                              void* d_out, int out_size) {
    const float* x = (const float*)d_in[0];  // [N*9]
    const float* w = (const float*)d_in[1];  // [8*9]
    const float* b = (const float*)d_in[2];  // [8]
    float* out = (float*)d_out;              // [N*9]

    int nrows = in_sizes[0] / 9;

    int ntiles = (nrows + ROWS_PER_TILE - 1) / ROWS_PER_TILE;
    int blocks = 148 * 6;
    if (blocks > ntiles) blocks = ntiles;
    affine_kernel<<<blocks, TPB>>>(x, w, b, out, nrows);
}

// round 9
// speedup vs baseline: 1.7719x; 1.7719x over previous
#include <cuda_runtime.h>
#include <cstdint>

// Composed affine map: 9 rows, each padded to 12 floats: [w0..w8, bias, 0, 0]
__device__ float g_aff[9 * 12];
__constant__ float c_aff[9 * 12];

// ---------------------------------------------------------------------------
// Kernel 1: compose the 8 conv layers into one affine map.
// Key fact: each column of the augmented 9x10 matrix evolves independently
// under conv+bias, so one lane owns one column in registers; no barriers.
// ---------------------------------------------------------------------------
__global__ void compose_kernel(const float* __restrict__ w,   // [8*9]
                               const float* __restrict__ b) { // [8]
    int c = threadIdx.x;          // column 0..9 (9 = bias column)
    if (c >= 10) return;

    float col[9];
#pragma unroll
    for (int o = 0; o < 9; o++) col[o] = (o == c) ? 1.0f : 0.0f;  // c==9 -> 0

    for (int d = 0; d < 8; d++) {
        float wd[9];
#pragma unroll
        for (int z = 0; z < 9; z++) wd[z] = __ldg(&w[d * 9 + z]);

        float nc[9];
#pragma unroll
        for (int o = 0; o < 9; o++) {
            int i = o / 3, j = o % 3;
            float acc = 0.0f;
#pragma unroll
            for (int di = -1; di <= 1; di++) {
#pragma unroll
                for (int dj = -1; dj <= 1; dj++) {
                    int ii = i + di, jj = j + dj;
                    if (ii >= 0 && ii < 3 && jj >= 0 && jj < 3)
                        acc += wd[(di + 1) * 3 + (dj + 1)] * col[ii * 3 + jj];
                }
            }
            nc[o] = acc;
        }
        float bd = (c == 9) ? __ldg(&b[d]) : 0.0f;
#pragma unroll
        for (int o = 0; o < 9; o++) col[o] = nc[o] + bd;
    }

#pragma unroll
    for (int o = 0; o < 9; o++) g_aff[o * 12 + c] = col[o];
    if (c < 9) { g_aff[c * 12 + 10] = 0.0f; g_aff[c * 12 + 11] = 0.0f; }
}

// ---------------------------------------------------------------------------
// Kernel 2: persistent TRIPLE-buffered TMA pipeline (A in __constant__).
//   prefetch tile+grid into buf (li+1)%3, gated by wait_group.read 1
//   (gating store is from 2 iterations ago -> off the critical path)
//   -> mbarrier wait -> in-place vector compute -> async bulk store.
// TPB=64, 256-row tiles (9216 B); 3 bufs = 27.7 KB smem -> 8 CTAs/SM.
// ---------------------------------------------------------------------------
#define TPB 64
#define RPT 4
#define ROWS_PER_TILE (TPB * RPT)            // 256
#define WORDS_PER_TILE (ROWS_PER_TILE * 9)   // 2304
#define BYTES_PER_TILE (WORDS_PER_TILE * 4)  // 9216
#define NBUF 3

__device__ __forceinline__ uint32_t smem_u32(const void* p) {
    uint32_t a;
    asm("{ .reg .u64 tmp; cvta.to.shared.u64 tmp, %1; cvt.u32.u64 %0, tmp; }"
        : "=r"(a) : "l"(p));
    return a;
}

__device__ __forceinline__ void mbar_wait(uint32_t mb, uint32_t parity) {
    uint32_t done;
    asm volatile(
        "{\n\t.reg .pred p;\n\t"
        "mbarrier.try_wait.parity.acquire.cta.shared::cta.b64 p, [%1], %2;\n\t"
        "selp.b32 %0, 1, 0, p;\n\t}"
        : "=r"(done) : "r"(mb), "r"(parity) : "memory");
    if (!done) {
        asm volatile(
            "{\n\t.reg .pred P1;\n\t"
            "WAIT_LOOP_%=:\n\t"
            "mbarrier.try_wait.parity.acquire.cta.shared::cta.b64 P1, [%0], %1, 0x989680;\n\t"
            "@P1 bra.uni WAIT_DONE_%=;\n\t"
            "bra.uni WAIT_LOOP_%=;\n\t"
            "WAIT_DONE_%=:\n\t}"
            :: "r"(mb), "r"(parity) : "memory");
    }
}

__global__ __launch_bounds__(TPB, 8)
void affine_kernel(const float* __restrict__ x,
                   float* __restrict__ out,
                   int nrows) {
    __shared__ __align__(128) float sx[NBUF][WORDS_PER_TILE];
    __shared__ __align__(8) unsigned long long mbar[NBUF];

    int t = threadIdx.x;
    int ntiles = (nrows + ROWS_PER_TILE - 1) / ROWS_PER_TILE;

    if (t == 0) {
#pragma unroll
        for (int i = 0; i < NBUF; i++)
            asm volatile("mbarrier.init.shared.b64 [%0], %1;"
                         :: "r"(smem_u32(&mbar[i])), "r"(1) : "memory");
    }
    __syncthreads();

    uint32_t s_mb[NBUF], s_bf[NBUF];
#pragma unroll
    for (int i = 0; i < NBUF; i++) {
        s_mb[i] = smem_u32(&mbar[i]);
        s_bf[i] = smem_u32(sx[i]);
    }

    // ---- prologue: prefetch my first tile (if full) into buffer 0 ----
    {
        long long tile0 = blockIdx.x;
        if (tile0 < ntiles && t == 0) {
            long long rows0 = (long long)nrows - tile0 * ROWS_PER_TILE;
            if (rows0 >= ROWS_PER_TILE) {
                const float* xg = x + tile0 * (long long)ROWS_PER_TILE * 9;
                asm volatile("mbarrier.arrive.expect_tx.shared.b64 _, [%0], %1;"
                             :: "r"(s_mb[0]), "r"((uint32_t)BYTES_PER_TILE) : "memory");
                asm volatile(
                    "cp.async.bulk.shared::cta.global.mbarrier::complete_tx::bytes "
                    "[%0], [%1], %2, [%3];"
                    :: "r"(s_bf[0]), "l"(xg), "r"((uint32_t)BYTES_PER_TILE), "r"(s_mb[0])
                    : "memory");
            }
        }
    }

    uint32_t ph[NBUF] = {0u, 0u, 0u};
    int li = 0;
    int b = 0;
    for (long long tile = blockIdx.x; tile < ntiles; tile += gridDim.x, li++) {
        int bn = (b + 1 == NBUF) ? 0 : b + 1;
        float* buf = sx[b];

        long long r0 = tile * ROWS_PER_TILE;
        int rows_here = (int)((((long long)nrows - r0) < ROWS_PER_TILE)
                                  ? (nrows - r0) : ROWS_PER_TILE);
        bool full = (rows_here == ROWS_PER_TILE);
        int cnt = rows_here * 9;
        const float* xg = x + r0 * 9;
        float*       og = out + r0 * 9;

        // ---- prefetch next tile into buffer bn ----
        long long ntile = tile + gridDim.x;
        if (ntile < ntiles && t == 0) {
            long long nrows_next = (long long)nrows - ntile * ROWS_PER_TILE;
            if (nrows_next >= ROWS_PER_TILE) {
                // buffer bn's last store was issued 2 iterations ago; allow
                // the most recent store to stay outstanding
                asm volatile("cp.async.bulk.wait_group.read 1;" ::: "memory");
                const float* xgn = x + ntile * (long long)ROWS_PER_TILE * 9;
                asm volatile("mbarrier.arrive.expect_tx.shared.b64 _, [%0], %1;"
                             :: "r"(s_mb[bn]), "r"((uint32_t)BYTES_PER_TILE) : "memory");
                asm volatile(
                    "cp.async.bulk.shared::cta.global.mbarrier::complete_tx::bytes "
                    "[%0], [%1], %2, [%3];"
                    :: "r"(s_bf[bn]), "l"(xgn), "r"((uint32_t)BYTES_PER_TILE), "r"(s_mb[bn])
                    : "memory");
            }
        }

        if (full) {
            // ---- consume TMA-loaded tile ----
            mbar_wait(s_mb[b], ph[b]);
            ph[b] ^= 1;

            float* chunk = &buf[t * 36];
            float v[20];
            float y[18];

#pragma unroll
            for (int g = 0; g < 2; g++) {
#pragma unroll
                for (int k = 0; k < 5; k++)
                    *(float4*)&v[4 * k] = *(const float4*)&chunk[16 * g + 4 * k];

                const float* xa = v + (g ? 2 : 0);
                const float* xb = xa + 9;

#pragma unroll
                for (int o = 0; o < 9; o++) {
                    float4 a0 = *(const float4*)&c_aff[o * 12 + 0];
                    float4 a1 = *(const float4*)&c_aff[o * 12 + 4];
                    float4 a2 = *(const float4*)&c_aff[o * 12 + 8]; // x=w8, y=bias

                    float acc = fmaf(a0.x, xa[0], a2.y);
                    acc = fmaf(a0.y, xa[1], acc);
                    acc = fmaf(a0.z, xa[2], acc);
                    acc = fmaf(a0.w, xa[3], acc);
                    acc = fmaf(a1.x, xa[4], acc);
                    acc = fmaf(a1.y, xa[5], acc);
                    acc = fmaf(a1.z, xa[6], acc);
                    acc = fmaf(a1.w, xa[7], acc);
                    y[o] = fmaf(a2.x, xa[8], acc);

                    float acd = fmaf(a0.x, xb[0], a2.y);
                    acd = fmaf(a0.y, xb[1], acd);
                    acd = fmaf(a0.z, xb[2], acd);
                    acd = fmaf(a0.w, xb[3], acd);
                    acd = fmaf(a1.x, xb[4], acd);
                    acd = fmaf(a1.y, xb[5], acd);
                    acd = fmaf(a1.z, xb[6], acd);
                    acd = fmaf(a1.w, xb[7], acd);
                    y[9 + o] = fmaf(a2.x, xb[8], acd);
                }

                if (g == 0) {
                    *(float4*)&chunk[0]  = *(const float4*)&y[0];
                    *(float4*)&chunk[4]  = *(const float4*)&y[4];
                    *(float4*)&chunk[8]  = *(const float4*)&y[8];
                    *(float4*)&chunk[12] = *(const float4*)&y[12];
                    *(float2*)&chunk[16] = *(const float2*)&y[16];
                } else {
                    *(float2*)&chunk[18] = *(const float2*)&y[0];
                    *(float4*)&chunk[20] = *(const float4*)&y[2];
                    *(float4*)&chunk[24] = *(const float4*)&y[6];
                    *(float4*)&chunk[28] = *(const float4*)&y[10];
                    *(float4*)&chunk[32] = *(const float4*)&y[14];
                }
            }

            __syncthreads();  // all y written before async store reads smem
            if (t == 0) {
                asm volatile("fence.proxy.async.shared::cta;" ::: "memory");
                asm volatile(
                    "cp.async.bulk.global.shared::cta.bulk_group [%0], [%1], %2;"
                    :: "l"(og), "r"(s_bf[b]), "r"((uint32_t)BYTES_PER_TILE)
                    : "memory");
                asm volatile("cp.async.bulk.commit_group;" ::: "memory");
            }
            // no wait: store drains while we move on
        } else {
            // ---- partial tile: synchronous fallback path ----
            if (t == 0) {
                asm volatile("cp.async.bulk.wait_group.read 0;" ::: "memory");
            }
            __syncthreads();
#pragma unroll
            for (int k = 0; k < (WORDS_PER_TILE / (TPB * 4)); k++) {
                int fi = (k * TPB + t) * 4;
                if (fi + 4 <= cnt) {
                    *(float4*)&buf[fi] = *(const float4*)&xg[fi];
                } else if (fi < cnt) {
                    for (int u = fi; u < cnt; u++) buf[u] = xg[u];
                }
            }
            __syncthreads();
            int lr0 = t * RPT;
            for (int lr = lr0; lr < lr0 + RPT && lr < rows_here; lr++) {
                float xp[9];
#pragma unroll
                for (int c = 0; c < 9; c++) xp[c] = buf[lr * 9 + c];
#pragma unroll
                for (int o = 0; o < 9; o++) {
                    float acc = c_aff[o * 12 + 9];
#pragma unroll
                    for (int c = 0; c < 9; c++)
                        acc = fmaf(c_aff[o * 12 + c], xp[c], acc);
                    buf[lr * 9 + o] = acc;
                }
            }
            __syncthreads();
#pragma unroll
            for (int k = 0; k < (WORDS_PER_TILE / (TPB * 4)); k++) {
                int fi = (k * TPB + t) * 4;
                if (fi + 4 <= cnt) {
                    *(float4*)&og[fi] = *(const float4*)&buf[fi];
                } else if (fi < cnt) {
                    for (int u = fi; u < cnt; u++) og[u] = buf[u];
                }
            }
        }

        b = bn;
    }

    // drain the last async stores before exit
    if (t == 0) {
        asm volatile("cp.async.bulk.wait_group 0;" ::: "memory");
    }
}

extern "C" void kernel_launch(void* const* d_in, const int* in_sizes, int n_in,
                              void* d_out, int out_size) {
    const float* x = (const float*)d_in[0];  // [N*9]
    const float* w = (const float*)d_in[1];  // [8*9]
    const float* b = (const float*)d_in[2];  // [8]
    float* out = (float*)d_out;              // [N*9]

    int nrows = in_sizes[0] / 9;

    compose_kernel<<<1, 32>>>(w, b);

    // Copy the composed affine map into __constant__ memory (D2D memcpy node)
    void* g_aff_ptr = nullptr;
    cudaGetSymbolAddress(&g_aff_ptr, g_aff);
    cudaMemcpyToSymbolAsync(c_aff, g_aff_ptr, 9 * 12 * sizeof(float), 0,
                            cudaMemcpyDeviceToDevice);

    int ntiles = (nrows + ROWS_PER_TILE - 1) / ROWS_PER_TILE;
    int blocks = 148 * 8;
    if (blocks > ntiles) blocks = ntiles;
    affine_kernel<<<blocks, TPB>>>(x, out, nrows);
}

// round 10
// speedup vs baseline: 1.9143x; 1.0804x over previous
#include <cuda_runtime.h>
#include <cstdint>

// ---------------------------------------------------------------------------
// Single fused kernel.
//   prologue: t0 issues first TMA prefetch; lanes 0..9 of warp 0 compose the
//             8 conv layers into the affine map A in REGISTERS (each lane owns
//             one column of the augmented 9x10 matrix; columns evolve
//             independently -> no barriers), write A to smem; one syncthreads.
//   loop:     persistent triple-buffered TMA pipeline over 256-row tiles:
//             prefetch next (wait_group.read 1 gate, 2 iters of slack) ->
//             mbarrier wait -> in-place vector compute -> async bulk store.
//   smem: 3*9216 + 448 + 24 = ~28.2 KB -> 8 CTAs/SM.
// ---------------------------------------------------------------------------
#define TPB 64
#define RPT 4
#define ROWS_PER_TILE (TPB * RPT)            // 256
#define WORDS_PER_TILE (ROWS_PER_TILE * 9)   // 2304
#define BYTES_PER_TILE (WORDS_PER_TILE * 4)  // 9216
#define NBUF 3

__device__ __forceinline__ uint32_t smem_u32(const void* p) {
    uint32_t a;
    asm("{ .reg .u64 tmp; cvta.to.shared.u64 tmp, %1; cvt.u32.u64 %0, tmp; }"
        : "=r"(a) : "l"(p));
    return a;
}

__device__ __forceinline__ void mbar_wait(uint32_t mb, uint32_t parity) {
    uint32_t done;
    asm volatile(
        "{\n\t.reg .pred p;\n\t"
        "mbarrier.try_wait.parity.acquire.cta.shared::cta.b64 p, [%1], %2;\n\t"
        "selp.b32 %0, 1, 0, p;\n\t}"
        : "=r"(done) : "r"(mb), "r"(parity) : "memory");
    if (!done) {
        asm volatile(
            "{\n\t.reg .pred P1;\n\t"
            "WAIT_LOOP_%=:\n\t"
            "mbarrier.try_wait.parity.acquire.cta.shared::cta.b64 P1, [%0], %1, 0x989680;\n\t"
            "@P1 bra.uni WAIT_DONE_%=;\n\t"
            "bra.uni WAIT_LOOP_%=;\n\t"
            "WAIT_DONE_%=:\n\t}"
            :: "r"(mb), "r"(parity) : "memory");
    }
}

__global__ __launch_bounds__(TPB, 8)
void affine_kernel(const float* __restrict__ x,
                   const float* __restrict__ w,    // [8*9]
                   const float* __restrict__ bias, // [8]
                   float* __restrict__ out,
                   int nrows) {
    __shared__ __align__(128) float sx[NBUF][WORDS_PER_TILE];
    __shared__ __align__(16) float sA[9 * 12];   // [w0..w8, bias, 0, 0] x 9
    __shared__ __align__(8) unsigned long long mbar[NBUF];

    int t = threadIdx.x;
    int ntiles = (nrows + ROWS_PER_TILE - 1) / ROWS_PER_TILE;

    if (t == 0) {
#pragma unroll
        for (int i = 0; i < NBUF; i++)
            asm volatile("mbarrier.init.shared.b64 [%0], %1;"
                         :: "r"(smem_u32(&mbar[i])), "r"(1) : "memory");
    }
    __syncthreads();

    uint32_t s_mb[NBUF], s_bf[NBUF];
#pragma unroll
    for (int i = 0; i < NBUF; i++) {
        s_mb[i] = smem_u32(&mbar[i]);
        s_bf[i] = smem_u32(sx[i]);
    }

    // ---- prologue: prefetch my first tile (if full) into buffer 0 ----
    {
        long long tile0 = blockIdx.x;
        if (tile0 < ntiles && t == 0) {
            long long rows0 = (long long)nrows - tile0 * ROWS_PER_TILE;
            if (rows0 >= ROWS_PER_TILE) {
                const float* xg = x + tile0 * (long long)ROWS_PER_TILE * 9;
                asm volatile("mbarrier.arrive.expect_tx.shared.b64 _, [%0], %1;"
                             :: "r"(s_mb[0]), "r"((uint32_t)BYTES_PER_TILE) : "memory");
                asm volatile(
                    "cp.async.bulk.shared::cta.global.mbarrier::complete_tx::bytes "
                    "[%0], [%1], %2, [%3];"
                    :: "r"(s_bf[0]), "l"(xg), "r"((uint32_t)BYTES_PER_TILE), "r"(s_mb[0])
                    : "memory");
            }
        }
    }

    // ---- compose A in registers, lanes 0..9 of warp 0; no barriers ----
    // (overlaps the first TMA load's DRAM latency)
    if (t < 10) {
        int c = t;               // column 0..8 = input elem, 9 = bias column
        float col[9];
#pragma unroll
        for (int o = 0; o < 9; o++) col[o] = (o == c) ? 1.0f : 0.0f;

        for (int d = 0; d < 8; d++) {
            float wd[9];
#pragma unroll
            for (int z = 0; z < 9; z++) wd[z] = __ldg(&w[d * 9 + z]);

            float nc[9];
#pragma unroll
            for (int o = 0; o < 9; o++) {
                int i = o / 3, j = o % 3;
                float acc = 0.0f;
#pragma unroll
                for (int di = -1; di <= 1; di++) {
#pragma unroll
                    for (int dj = -1; dj <= 1; dj++) {
                        int ii = i + di, jj = j + dj;
                        if (ii >= 0 && ii < 3 && jj >= 0 && jj < 3)
                            acc += wd[(di + 1) * 3 + (dj + 1)] * col[ii * 3 + jj];
                    }
                }
                nc[o] = acc;
            }
            float bd = (c == 9) ? __ldg(&bias[d]) : 0.0f;
#pragma unroll
            for (int o = 0; o < 9; o++) col[o] = nc[o] + bd;
        }

#pragma unroll
        for (int o = 0; o < 9; o++) sA[o * 12 + c] = col[o];
        if (c < 9) { sA[c * 12 + 10] = 0.0f; sA[c * 12 + 11] = 0.0f; }
    }
    __syncthreads();   // A visible to all warps

    uint32_t ph[NBUF] = {0u, 0u, 0u};
    int b = 0;
    for (long long tile = blockIdx.x; tile < ntiles; tile += gridDim.x) {
        int bn = (b + 1 == NBUF) ? 0 : b + 1;
        float* buf = sx[b];

        long long r0 = tile * ROWS_PER_TILE;
        int rows_here = (int)((((long long)nrows - r0) < ROWS_PER_TILE)
                                  ? (nrows - r0) : ROWS_PER_TILE);
        bool full = (rows_here == ROWS_PER_TILE);
        int cnt = rows_here * 9;
        const float* xg = x + r0 * 9;
        float*       og = out + r0 * 9;

        // ---- prefetch next tile into buffer bn ----
        long long ntile = tile + gridDim.x;
        if (ntile < ntiles && t == 0) {
            long long nrows_next = (long long)nrows - ntile * ROWS_PER_TILE;
            if (nrows_next >= ROWS_PER_TILE) {
                // buffer bn's store was issued 2 iterations ago; allow the
                // most recent store to stay outstanding
                asm volatile("cp.async.bulk.wait_group.read 1;" ::: "memory");
                const float* xgn = x + ntile * (long long)ROWS_PER_TILE * 9;
                asm volatile("mbarrier.arrive.expect_tx.shared.b64 _, [%0], %1;"
                             :: "r"(s_mb[bn]), "r"((uint32_t)BYTES_PER_TILE) : "memory");
                asm volatile(
                    "cp.async.bulk.shared::cta.global.mbarrier::complete_tx::bytes "
                    "[%0], [%1], %2, [%3];"
                    :: "r"(s_bf[bn]), "l"(xgn), "r"((uint32_t)BYTES_PER_TILE), "r"(s_mb[bn])
                    : "memory");
            }
        }

        if (full) {
            // ---- consume TMA-loaded tile ----
            mbar_wait(s_mb[b], ph[b]);
            ph[b] ^= 1;

            float* chunk = &buf[t * 36];
            float v[20];
            float y[18];

#pragma unroll
            for (int g = 0; g < 2; g++) {
#pragma unroll
                for (int k = 0; k < 5; k++)
                    *(float4*)&v[4 * k] = *(const float4*)&chunk[16 * g + 4 * k];

                const float* xa = v + (g ? 2 : 0);
                const float* xb = xa + 9;

#pragma unroll
                for (int o = 0; o < 9; o++) {
                    float4 a0 = *(const float4*)&sA[o * 12 + 0];
                    float4 a1 = *(const float4*)&sA[o * 12 + 4];
                    float4 a2 = *(const float4*)&sA[o * 12 + 8]; // x=w8, y=bias

                    float acc = fmaf(a0.x, xa[0], a2.y);
                    acc = fmaf(a0.y, xa[1], acc);
                    acc = fmaf(a0.z, xa[2], acc);
                    acc = fmaf(a0.w, xa[3], acc);
                    acc = fmaf(a1.x, xa[4], acc);
                    acc = fmaf(a1.y, xa[5], acc);
                    acc = fmaf(a1.z, xa[6], acc);
                    acc = fmaf(a1.w, xa[7], acc);
                    y[o] = fmaf(a2.x, xa[8], acc);

                    float acd = fmaf(a0.x, xb[0], a2.y);
                    acd = fmaf(a0.y, xb[1], acd);
                    acd = fmaf(a0.z, xb[2], acd);
                    acd = fmaf(a0.w, xb[3], acd);
                    acd = fmaf(a1.x, xb[4], acd);
                    acd = fmaf(a1.y, xb[5], acd);
                    acd = fmaf(a1.z, xb[6], acd);
                    acd = fmaf(a1.w, xb[7], acd);
                    y[9 + o] = fmaf(a2.x, xb[8], acd);
                }

                if (g == 0) {
                    *(float4*)&chunk[0]  = *(const float4*)&y[0];
                    *(float4*)&chunk[4]  = *(const float4*)&y[4];
                    *(float4*)&chunk[8]  = *(const float4*)&y[8];
                    *(float4*)&chunk[12] = *(const float4*)&y[12];
                    *(float2*)&chunk[16] = *(const float2*)&y[16];
                } else {
                    *(float2*)&chunk[18] = *(const float2*)&y[0];
                    *(float4*)&chunk[20] = *(const float4*)&y[2];
                    *(float4*)&chunk[24] = *(const float4*)&y[6];
                    *(float4*)&chunk[28] = *(const float4*)&y[10];
                    *(float4*)&chunk[32] = *(const float4*)&y[14];
                }
            }

            __syncthreads();  // all y written before async store reads smem
            if (t == 0) {
                asm volatile("fence.proxy.async.shared::cta;" ::: "memory");
                asm volatile(
                    "cp.async.bulk.global.shared::cta.bulk_group [%0], [%1], %2;"
                    :: "l"(og), "r"(s_bf[b]), "r"((uint32_t)BYTES_PER_TILE)
                    : "memory");
                asm volatile("cp.async.bulk.commit_group;" ::: "memory");
            }
            // no wait: store drains while we move on
        } else {
            // ---- partial tile: synchronous fallback path ----
            if (t == 0) {
                asm volatile("cp.async.bulk.wait_group.read 0;" ::: "memory");
            }
            __syncthreads();
#pragma unroll
            for (int k = 0; k < (WORDS_PER_TILE / (TPB * 4)); k++) {
                int fi = (k * TPB + t) * 4;
                if (fi + 4 <= cnt) {
                    *(float4*)&buf[fi] = *(const float4*)&xg[fi];
                } else if (fi < cnt) {
                    for (int u = fi; u < cnt; u++) buf[u] = xg[u];
                }
            }
            __syncthreads();
            int lr0 = t * RPT;
            for (int lr = lr0; lr < lr0 + RPT && lr < rows_here; lr++) {
                float xp[9];
#pragma unroll
                for (int c = 0; c < 9; c++) xp[c] = buf[lr * 9 + c];
#pragma unroll
                for (int o = 0; o < 9; o++) {
                    float acc = sA[o * 12 + 9];
#pragma unroll
                    for (int c = 0; c < 9; c++)
                        acc = fmaf(sA[o * 12 + c], xp[c], acc);
                    buf[lr * 9 + o] = acc;
                }
            }
            __syncthreads();
#pragma unroll
            for (int k = 0; k < (WORDS_PER_TILE / (TPB * 4)); k++) {
                int fi = (k * TPB + t) * 4;
                if (fi + 4 <= cnt) {
                    *(float4*)&og[fi] = *(const float4*)&buf[fi];
                } else if (fi < cnt) {
                    for (int u = fi; u < cnt; u++) og[u] = buf[u];
                }
            }
        }

        b = bn;
    }

    // drain the last async stores before exit
    if (t == 0) {
        asm volatile("cp.async.bulk.wait_group 0;" ::: "memory");
    }
}

extern "C" void kernel_launch(void* const* d_in, const int* in_sizes, int n_in,
                              void* d_out, int out_size) {
    const float* x = (const float*)d_in[0];  // [N*9]
    const float* w = (const float*)d_in[1];  // [8*9]
    const float* b = (const float*)d_in[2];  // [8]
    float* out = (float*)d_out;              // [N*9]

    int nrows = in_sizes[0] / 9;

    int ntiles = (nrows + ROWS_PER_TILE - 1) / ROWS_PER_TILE;
    int blocks = 148 * 8;
    if (blocks > ntiles) blocks = ntiles;
    affine_kernel<<<blocks, TPB>>>(x, w, b, out, nrows);
}